// round 3
// baseline (speedup 1.0000x reference)
#include <cuda_runtime.h>

#define HH 1024
#define WW 1024
#define HWSZ (HH * WW)

// Scratch: ping-pong h/c state + decoder input (constant across decoder steps).
__device__ float g_h[2][HWSZ];
__device__ float g_c[2][HWSZ];
__device__ float g_x[HWSZ];

// [0] = encoder, [1] = decoder. w layout: [gate(4)][chan(2)][ky(3)][kx(3)]
__constant__ float c_w[2][72];
__constant__ float c_b[2][8];   // only 4 used per set

__device__ __forceinline__ float fsig(float v) {
    // 1 / (1 + e^-v): ex2.approx + rcp.approx (~2 ulp)
    return __fdividef(1.0f, 1.0f + __expf(-v));
}
__device__ __forceinline__ float ftanh_fast(float v) {
    // tanh(v) = 2/(1+e^-2v) - 1
    return __fdividef(2.0f, 1.0f + __expf(-2.0f * v)) - 1.0f;
}

// One ConvLSTM cell step, fused: conv(concat(x,h)) -> gates -> (h,c) update.
// WS selects weight set, FIRST means h=c=0 (skip those loads/FMAs),
// ENC means x = xbase + frame*HW with frame = epoch + s (else x = xbase, frame = s).
// Inactive steps (frame >= *p_lim) pass state through unchanged so the launch
// count is input-independent (graph-capture safe for any epoch/T_en/T_de).
template <int WS, bool FIRST, bool ENC>
__global__ __launch_bounds__(256) void step_kernel(
    const float* __restrict__ xbase,
    const float* __restrict__ h_in,
    const float* __restrict__ c_in,
    float* __restrict__ h_out,
    float* __restrict__ c_out,
    const int* __restrict__ p_epoch,
    const int* __restrict__ p_lim,
    int s)
{
    const int x0 = (blockIdx.x * blockDim.x + threadIdx.x) * 4;
    const int y  = blockIdx.y * blockDim.y + threadIdx.y;
    const size_t base = (size_t)y * WW + x0;

    int frame = s;
    if (ENC) frame += p_epoch[0];
    const bool active = frame < p_lim[0];

    if (!active) {
        float4 hz, cz;
        if (FIRST) {
            hz = make_float4(0.f, 0.f, 0.f, 0.f);
            cz = hz;
        } else {
            hz = *(const float4*)(h_in + base);
            cz = *(const float4*)(c_in + base);
        }
        *(float4*)(h_out + base) = hz;
        *(float4*)(c_out + base) = cz;
        return;
    }

    const float* xp = ENC ? (xbase + (size_t)frame * HWSZ) : xbase;

    // 3x6 neighborhoods for 4 output pixels (SAME zero padding).
    float xv[3][6];
    float hv[3][6];
#pragma unroll
    for (int dy = 0; dy < 3; dy++) {
        const int r = y + dy - 1;
        const bool rv = (r >= 0) && (r < HH);
        const size_t ro = (size_t)r * WW;

        float4 mx = make_float4(0.f, 0.f, 0.f, 0.f);
        float lx = 0.f, rx = 0.f;
        if (rv) {
            mx = *(const float4*)(xp + ro + x0);
            if (x0 > 0)       lx = xp[ro + x0 - 1];
            if (x0 + 4 < WW)  rx = xp[ro + x0 + 4];
        }
        xv[dy][0] = lx;   xv[dy][1] = mx.x; xv[dy][2] = mx.y;
        xv[dy][3] = mx.z; xv[dy][4] = mx.w; xv[dy][5] = rx;

        if (!FIRST) {
            float4 mh = make_float4(0.f, 0.f, 0.f, 0.f);
            float lh = 0.f, rh = 0.f;
            if (rv) {
                mh = *(const float4*)(h_in + ro + x0);
                if (x0 > 0)      lh = h_in[ro + x0 - 1];
                if (x0 + 4 < WW) rh = h_in[ro + x0 + 4];
            }
            hv[dy][0] = lh;   hv[dy][1] = mh.x; hv[dy][2] = mh.y;
            hv[dy][3] = mh.z; hv[dy][4] = mh.w; hv[dy][5] = rh;
        }
    }

    // acc[j][g]: j = pixel within the 4-wide strip, g = gate (i,f,o,g).
    // Weight-outer / pixel-inner order so each LDCU'd weight is reused x4.
    float acc[4][4];
#pragma unroll
    for (int j = 0; j < 4; j++)
#pragma unroll
        for (int g = 0; g < 4; g++)
            acc[j][g] = c_b[WS][g];

#pragma unroll
    for (int dy = 0; dy < 3; dy++) {
#pragma unroll
        for (int dx = 0; dx < 3; dx++) {
#pragma unroll
            for (int g = 0; g < 4; g++) {
                const float wx = c_w[WS][g * 18 + dy * 3 + dx];
#pragma unroll
                for (int j = 0; j < 4; j++)
                    acc[j][g] += wx * xv[dy][j + dx];
            }
            if (!FIRST) {
#pragma unroll
                for (int g = 0; g < 4; g++) {
                    const float wh = c_w[WS][g * 18 + 9 + dy * 3 + dx];
#pragma unroll
                    for (int j = 0; j < 4; j++)
                        acc[j][g] += wh * hv[dy][j + dx];
                }
            }
        }
    }

    float cp[4] = {0.f, 0.f, 0.f, 0.f};
    if (!FIRST) {
        const float4 cc = *(const float4*)(c_in + base);
        cp[0] = cc.x; cp[1] = cc.y; cp[2] = cc.z; cp[3] = cc.w;
    }

    float hnv[4], cnv[4];
#pragma unroll
    for (int j = 0; j < 4; j++) {
        const float ig = fsig(acc[j][0]);
        const float fg = fsig(acc[j][1]);
        const float og = fsig(acc[j][2]);
        const float gg = ftanh_fast(acc[j][3]);
        const float cnew = FIRST ? (ig * gg) : (fg * cp[j] + ig * gg);
        cnv[j] = cnew;
        hnv[j] = og * ftanh_fast(cnew);
    }
    *(float4*)(h_out + base) = make_float4(hnv[0], hnv[1], hnv[2], hnv[3]);
    *(float4*)(c_out + base) = make_float4(cnv[0], cnv[1], cnv[2], cnv[3]);
}

extern "C" void kernel_launch(void* const* d_in, const int* in_sizes, int n_in,
                              void* d_out, int out_size)
{
    const float* data  = (const float*)d_in[0];   // [20,1,1,1024,1024]
    const float* enc_w = (const float*)d_in[1];   // [4,2,3,3]
    const float* enc_b = (const float*)d_in[2];   // [4]
    const float* dec_w = (const float*)d_in[3];   // [4,2,3,3]
    const float* dec_b = (const float*)d_in[4];   // [4]
    const int*   epoch = (const int*)d_in[5];
    const int*   t_en  = (const int*)d_in[6];
    const int*   t_de  = (const int*)d_in[7];

    // Weights/bias into constant bank (D2D async copies: legal graph nodes).
    cudaMemcpyToSymbolAsync(c_w, enc_w, 72 * sizeof(float), 0,
                            cudaMemcpyDeviceToDevice, 0);
    cudaMemcpyToSymbolAsync(c_w, dec_w, 72 * sizeof(float), 72 * sizeof(float),
                            cudaMemcpyDeviceToDevice, 0);
    cudaMemcpyToSymbolAsync(c_b, enc_b, 4 * sizeof(float), 0,
                            cudaMemcpyDeviceToDevice, 0);
    cudaMemcpyToSymbolAsync(c_b, dec_b, 4 * sizeof(float), 8 * sizeof(float),
                            cudaMemcpyDeviceToDevice, 0);

    float *hbuf = nullptr, *cbuf = nullptr, *xdec = nullptr;
    cudaGetSymbolAddress((void**)&hbuf, g_h);
    cudaGetSymbolAddress((void**)&cbuf, g_c);
    cudaGetSymbolAddress((void**)&xdec, g_x);
    float* hA = hbuf;        float* hB = hbuf + HWSZ;
    float* cA = cbuf;        float* cB = cbuf + HWSZ;

    const dim3 blk(64, 4);
    const dim3 grd(WW / (64 * 4), HH / 4);   // (4, 256)

    // ---- Encoder: 20 steps over data[epoch + s], active while frame < T_en ----
    step_kernel<0, true, true><<<grd, blk>>>(data, hA, cA, hB, cB, epoch, t_en, 0);
    for (int s = 1; s < 20; s++) {
        float* hi = (s & 1) ? hB : hA;
        float* ho = (s & 1) ? hA : hB;
        float* ci = (s & 1) ? cB : cA;
        float* co = (s & 1) ? cA : cB;
        step_kernel<0, false, true><<<grd, blk>>>(data, hi, ci, ho, co, epoch, t_en, s);
    }
    // After s=19 (odd), final encoder h/c live in buffer A.
    cudaMemcpyAsync(xdec, hA, HWSZ * sizeof(float), cudaMemcpyDeviceToDevice, 0);

    // ---- Decoder: 20 steps with constant input x = encoder h, fresh (h0,c0) ----
    step_kernel<1, true, false><<<grd, blk>>>(xdec, hA, cA, hB, cB, epoch, t_de, 0);
    for (int s = 1; s < 20; s++) {
        float* hi = (s & 1) ? hB : hA;
        float* ho = (s & 1) ? hA : hB;
        float* ci = (s & 1) ? cB : cA;
        float* co = (s & 1) ? cA : cB;
        step_kernel<1, false, false><<<grd, blk>>>(xdec, hi, ci, ho, co, epoch, t_de, s);
    }
    // Final decoder h in buffer A -> output [1024,1024] float32.
    cudaMemcpyAsync(d_out, hA, HWSZ * sizeof(float), cudaMemcpyDeviceToDevice, 0);
}